// round 17
// baseline (speedup 1.0000x reference)
#include <cuda_runtime.h>
#include <cuda_bf16.h>
#include <math.h>
#include <stdint.h>

#define NW 6

// U = Ur + i*Ui, 64x64 bf16 each, row-major [row*64 + col].
__device__ __align__(16) __nv_bfloat16 d_Ur[64 * 64];
__device__ __align__(16) __nv_bfloat16 d_Ui[64 * 64];

// ---------------- complex helpers ----------------
__device__ __forceinline__ float2 cmul(float2 a, float2 b) {
    return make_float2(a.x * b.x - a.y * b.y, a.x * b.y + a.y * b.x);
}
__device__ __forceinline__ float2 cadd(float2 a, float2 b) {
    return make_float2(a.x + b.x, a.y + b.y);
}
__device__ __forceinline__ float2 cscale(float2 a, float s) {
    return make_float2(a.x * s, a.y * s);
}
__device__ __forceinline__ float2 shflxor(float2 v, int m) {
    v.x = __shfl_xor_sync(0xffffffffu, v.x, m);
    v.y = __shfl_xor_sync(0xffffffffu, v.y, m);
    return v;
}

// ================= build_U (64 blocks x 32 threads) =================
__device__ __forceinline__ void apply_diag(float2& s0, float2& s1, int lane, int w,
                                           float2 d0, float2 d1) {
    int bit = 5 - w;
    if (bit == 0) {
        s0 = cmul(s0, d0);
        s1 = cmul(s1, d1);
    } else {
        int mb = (lane >> (bit - 1)) & 1;
        float2 d = mb ? d1 : d0;
        s0 = cmul(s0, d);
        s1 = cmul(s1, d);
    }
}

__device__ __forceinline__ void apply1(float2& s0, float2& s1, int lane, int w,
                                       float2 u00, float2 u01, float2 u10, float2 u11) {
    int bit = 5 - w;
    if (bit == 0) {
        float2 t0 = cadd(cmul(u00, s0), cmul(u01, s1));
        float2 t1 = cadd(cmul(u10, s0), cmul(u11, s1));
        s0 = t0; s1 = t1;
    } else {
        int lm = 1 << (bit - 1);
        float2 p0 = shflxor(s0, lm);
        float2 p1 = shflxor(s1, lm);
        int mb = (lane >> (bit - 1)) & 1;
        if (mb == 0) {
            s0 = cadd(cmul(u00, s0), cmul(u01, p0));
            s1 = cadd(cmul(u00, s1), cmul(u01, p1));
        } else {
            s0 = cadd(cmul(u10, p0), cmul(u11, s0));
            s1 = cadd(cmul(u10, p1), cmul(u11, s1));
        }
    }
}

__device__ __forceinline__ float2 bsu(float2 s, float2 p, int na, int nb,
                                      float c, float sn, float c2, float ex, float ey) {
    if (na == nb) return na ? cscale(s, c2) : s;
    if (na == 0) {
        return make_float2(c * s.x + sn * (ex * p.x - ey * p.y),
                           c * s.y + sn * (ex * p.y + ey * p.x));
    } else {
        return make_float2(c * s.x - sn * (ex * p.x + ey * p.y),
                           c * s.y - sn * (ex * p.y - ey * p.x));
    }
}

__device__ __forceinline__ void apply_bs(float2& s0, float2& s1, int lane, int w,
                                         float th, float ph) {
    float c, sn;
    __sincosf(th, &sn, &c);
    float c2 = c * c - sn * sn;
    float ex, ey;
    __sincosf(ph, &ey, &ex);
    int ba = 5 - w, bb = 4 - w;
    float2 p0, p1;
    if (bb >= 1) {
        int lm = ((1 << ba) | (1 << bb)) >> 1;
        p0 = shflxor(s0, lm);
        p1 = shflxor(s1, lm);
    } else {
        p0 = shflxor(s1, 1);
        p1 = shflxor(s0, 1);
    }
    int n0 = lane * 2, n1 = lane * 2 + 1;
    s0 = bsu(s0, p0, (n0 >> ba) & 1, (n0 >> bb) & 1, c, sn, c2, ex, ey);
    s1 = bsu(s1, p1, (n1 >> ba) & 1, (n1 >> bb) & 1, c, sn, c2, ex, ey);
}

__global__ void build_W_kernel(const float* __restrict__ var) {
    int col = blockIdx.x;
    int lane = threadIdx.x;
    float2 s0 = make_float2(0.f, 0.f), s1 = make_float2(0.f, 0.f);
    if (lane * 2 == col) s0.x = 1.f;
    if (lane * 2 + 1 == col) s1.x = 1.f;

    for (int l = 0; l < 2; l++) {
        const float* v = var + 50 * l;
        for (int i = 0; i < 5; i++)
            apply_bs(s0, s1, lane, i, __ldg(v + 2 * i), __ldg(v + 2 * i + 1));
        for (int w = 0; w < NW; w++) {
            float ph = __ldg(v + 10 + w);
            float sp, cp; __sincosf(ph, &sp, &cp);
            apply_diag(s0, s1, lane, w, make_float2(1.f, 0.f), make_float2(cp, sp));
        }
        for (int w = 0; w < NW; w++) {
            float r = __ldg(v + 16 + w);
            float e = __expf(r);
            float sech = __fdividef(2.f * e, fmaf(e, e, 1.f));
            float sr = sqrtf(sech);
            apply_diag(s0, s1, lane, w, make_float2(sr, 0.f), make_float2(sech * sr, 0.f));
        }
        for (int i = 0; i < 5; i++)
            apply_bs(s0, s1, lane, i, __ldg(v + 22 + 2 * i), __ldg(v + 23 + 2 * i));
        for (int w = 0; w < NW; w++) {
            float ph = __ldg(v + 32 + w);
            float sp, cp; __sincosf(ph, &sp, &cp);
            apply_diag(s0, s1, lane, w, make_float2(1.f, 0.f), make_float2(cp, sp));
        }
        for (int w = 0; w < NW; w++) {
            float r = __ldg(v + 38 + w);
            float pref = __expf(-0.5f * r * r);
            apply1(s0, s1, lane, w,
                   make_float2(pref, 0.f), make_float2(-pref * r, 0.f),
                   make_float2(pref * r, 0.f), make_float2(pref * (1.f - r * r), 0.f));
        }
        for (int w = 0; w < NW; w++) {
            float ph = __ldg(v + 44 + w);
            float sp, cp; __sincosf(ph, &sp, &cp);
            apply_diag(s0, s1, lane, w, make_float2(1.f, 0.f), make_float2(cp, sp));
        }
    }
    int k = col;
#pragma unroll
    for (int h = 0; h < 2; h++) {
        float2 u = h ? s1 : s0;
        int r = 2 * lane + h;
        d_Ur[r * 64 + k] = __float2bfloat16(u.x);
        d_Ui[r * 64 + k] = __float2bfloat16(u.y);
    }
}

// ================= main fused kernel =================
// 256 threads/CTA, 128 samples/CTA, 8 warps x 16 samples, 2 CTAs/SM.
// Karatsuba-style: br = ar*Ur^T - ai*Ui^T, bi = ar*Ui^T + ai*Ur^T.
// Epilogue: residual x read from global (sector-perfect per quad),
// LN result stored directly to global. Xs = prologue staging only.
// smem layout (bytes):
//   Ar 128x72 bf16 [0,18432) ; Ai 128x72 bf16 [18432,36864) ;
//   Urs 64x72 bf16 [36864,46080) ; Uis 64x72 bf16 [46080,55296) ;
//   Xs 128x65 f32 [55296,88576) ; gb 128 f32 [88576,89088).

static constexpr int AS2 = 72;                         // row stride, bf16 units
static constexpr uint32_t AI_OFF = 128u * AS2 * 2u;    // 18432
static constexpr uint32_t UR_OFF = AI_OFF * 2u;        // 36864
static constexpr uint32_t UI_OFF = UR_OFF + 64u * AS2 * 2u;   // 46080
static constexpr uint32_t X_OFF  = UI_OFF + 64u * AS2 * 2u;   // 55296
static constexpr uint32_t GB_OFF = X_OFF + 128u * 65u * 4u;   // 88576
static constexpr uint32_t SMEM_DYN = GB_OFF + 512u;    // 89088

__device__ __forceinline__ void mma16816(float c[4], const uint32_t a[4],
                                         uint32_t b0, uint32_t b1) {
    asm("mma.sync.aligned.m16n8k16.row.col.f32.bf16.bf16.f32 "
        "{%0,%1,%2,%3}, {%4,%5,%6,%7}, {%8,%9}, {%0,%1,%2,%3};"
        : "+f"(c[0]), "+f"(c[1]), "+f"(c[2]), "+f"(c[3])
        : "r"(a[0]), "r"(a[1]), "r"(a[2]), "r"(a[3]), "r"(b0), "r"(b1));
}

__device__ __forceinline__ void ldmx4(uint32_t r[4], uint32_t addr) {
    asm volatile("ldmatrix.sync.aligned.m8n8.x4.shared.b16 {%0,%1,%2,%3}, [%4];"
                 : "=r"(r[0]), "=r"(r[1]), "=r"(r[2]), "=r"(r[3]) : "r"(addr));
}

__global__ void __launch_bounds__(256, 2)
ffb_mma_kernel(const float* __restrict__ x,
               const float* __restrict__ gamma_, const float* __restrict__ beta_,
               float* __restrict__ out, int nsamp) {
    extern __shared__ __align__(16) unsigned char dsm[];
    __nv_bfloat16* Ar  = (__nv_bfloat16*)(dsm);
    __nv_bfloat16* Ai  = (__nv_bfloat16*)(dsm + AI_OFF);
    __nv_bfloat16* Urs = (__nv_bfloat16*)(dsm + UR_OFF);
    __nv_bfloat16* Uis = (__nv_bfloat16*)(dsm + UI_OFF);
    float* Xs          = (float*)(dsm + X_OFF);
    float* gb          = (float*)(dsm + GB_OFF);

    int tid  = threadIdx.x;
    int wid  = tid >> 5;
    int lane = tid & 31;
    int g    = lane >> 2;
    int t4   = lane & 3;

    // ---- stage x tile (coalesced float4) into padded Xs ----
    {
        const float4* x4 = (const float4*)x;
        size_t tb4 = (size_t)blockIdx.x * 2048;
        size_t lim = (size_t)nsamp * 16;
#pragma unroll
        for (int i = 0; i < 8; i++) {
            int e = tid + 256 * i;
            size_t gaddr = tb4 + e;
            float4 v = (gaddr < lim) ? __ldg(x4 + gaddr) : make_float4(0.f, 0.f, 0.f, 0.f);
            int row = e >> 4, c = (e & 15) * 4;
            float* p = Xs + row * 65 + c;
            p[0] = v.x; p[1] = v.y; p[2] = v.z; p[3] = v.w;
        }
    }
    // ---- stage Ur, Ui (coalesced): 512 float4 each; row = e>>3, col = e&7 ----
    {
        const float4* srcR = (const float4*)d_Ur;
        const float4* srcI = (const float4*)d_Ui;
#pragma unroll
        for (int i = 0; i < 2; i++) {
            int e = tid + 256 * i;
            int row = e >> 3, c = e & 7;
            *(float4*)(Urs + row * AS2 + c * 8) = __ldg(srcR + e);
            *(float4*)(Uis + row * AS2 + c * 8) = __ldg(srcI + e);
        }
    }
    if (tid < 16)      ((float4*)gb)[tid] = ((const float4*)gamma_)[tid];
    else if (tid < 32) ((float4*)gb)[tid] = ((const float4*)beta_)[tid - 16];
    __syncthreads();

    // ---- prologue (tid<128): amplitudes from Xs -> Ar/Ai rows ----
    if (tid < 128) {
        const float* Xrow = Xs + tid * 65;
        float2 P3[8], Q3[8];

#pragma unroll
        for (int hf = 0; hf < 2; hf++) {
            int wb = 3 * hf;
            float e2v[3], qv[3], rdv[3];
            float2 cs[3];
            float Pp = 1.f, Ep = 1.f, rdsq = 0.f;
#pragma unroll
            for (int i = 0; i < 3; i++) {
                int w = wb + i;
                float r1   = Xrow[2 * w];
                float rd   = Xrow[28 + 2 * w];
                float phid = Xrow[29 + 2 * w];
                float phik = Xrow[40 + w];
                float r2   = Xrow[46 + 2 * w];
                float phir = Xrow[58 + w];
                float e1 = __expf(r1);
                float e2 = __expf(r2);
                e2v[i] = e2;
                qv[i] = fmaf(e2, e2, 1.f);
                Pp *= fmaf(e1, e1, 1.f);
                Ep *= e1 * e2;
                rdv[i] = rd;
                rdsq = fmaf(rd, rd, rdsq);
                float th = phid + phik + phir;
                float sth, cth;
                __sincosf(th, &sth, &cth);
                cs[i] = make_float2(cth, sth);
            }
            float prefH = __expf(-0.5f * rdsq);
            float Qp = qv[0] * qv[1] * qv[2];
            float rQ  = __fdividef(1.f, Qp);
            float rPQ = __fdividef(1.f, Pp * Qp);
            float sH = 64.f * Ep * rPQ;                  // prod sech1*sech2
            float AH = prefH * sqrtf(sH);
            float2 T0 = cscale(cs[0], rdv[0] * 2.f * e2v[0] * qv[1] * qv[2] * rQ);
            float2 T1 = cscale(cs[1], rdv[1] * 2.f * e2v[1] * qv[0] * qv[2] * rQ);
            float2 T2 = cscale(cs[2], rdv[2] * 2.f * e2v[2] * qv[0] * qv[1] * rQ);

            float2* H = hf ? Q3 : P3;
            H[0] = make_float2(AH, 0.f);
            H[1] = cscale(T2, AH);
            H[2] = cscale(T1, AH);
            H[3] = cmul(H[2], T2);
            H[4] = cscale(T0, AH);
            H[5] = cmul(H[4], T2);
            H[6] = cmul(H[4], T1);
            H[7] = cmul(H[6], T2);
        }

        __nv_bfloat16* arowR = Ar + tid * AS2;
        __nv_bfloat16* arowI = Ai + tid * AS2;
        int stag = lane >> 3;   // conflict-free stagger (stride-72 rows)
#pragma unroll
        for (int i = 0; i < 32; i++) {
            int j0 = (i + stag) & 31;
            int ja = 2 * j0, jb = 2 * j0 + 1;
            float2 aa = cmul(P3[ja >> 3], Q3[ja & 7]);
            float2 ab = cmul(P3[jb >> 3], Q3[jb & 7]);
            *(__nv_bfloat162*)(arowR + 2 * j0) =
                __nv_bfloat162(__float2bfloat16(aa.x), __float2bfloat16(ab.x));
            *(__nv_bfloat162*)(arowI + 2 * j0) =
                __nv_bfloat162(__float2bfloat16(aa.y), __float2bfloat16(ab.y));
        }
    }
    __syncthreads();

    // ---- GEMM: warp computes br/bi [16 x 64] for samples [wid*16, wid*16+16) ----
    int warpM = wid * 16;
    float cbr[8][4], cbi[8][4];
#pragma unroll
    for (int nt = 0; nt < 8; nt++)
#pragma unroll
        for (int e = 0; e < 4; e++) { cbr[nt][e] = 0.f; cbi[nt][e] = 0.f; }

    uint32_t arBase = (uint32_t)__cvta_generic_to_shared(Ar);
    uint32_t aiBase = (uint32_t)__cvta_generic_to_shared(Ai);
    uint32_t urBase = (uint32_t)__cvta_generic_to_shared(Urs);
    uint32_t uiBase = (uint32_t)__cvta_generic_to_shared(Uis);
    uint32_t aoff = (uint32_t)(((warpM + (lane & 15)) * AS2 + ((lane >> 4) << 3)) * 2);
    uint32_t boff = (uint32_t)(((((lane & 7) + ((lane >> 4) << 3)) * AS2) +
                                (((lane >> 3) & 1) << 3)) * 2);
    uint32_t aAddrR = arBase + aoff;
    uint32_t aAddrI = aiBase + aoff;
    uint32_t bAddrR = urBase + boff;
    uint32_t bAddrI = uiBase + boff;

#pragma unroll
    for (int ko = 0; ko < 4; ko++) {
        uint32_t ar[4], ai[4], nai[4];
        ldmx4(ar, aAddrR + (uint32_t)(ko * 32));
        ldmx4(ai, aAddrI + (uint32_t)(ko * 32));
#pragma unroll
        for (int j = 0; j < 4; j++) nai[j] = ai[j] ^ 0x80008000u;
#pragma unroll
        for (int nt2 = 0; nt2 < 4; nt2++) {
            uint32_t ur[4], ui[4];
            uint32_t toff = (uint32_t)(nt2 * 16 * AS2 * 2 + ko * 32);
            ldmx4(ur, bAddrR + toff);
            ldmx4(ui, bAddrI + toff);
            mma16816(cbr[nt2 * 2],     ar,  ur[0], ur[1]);
            mma16816(cbr[nt2 * 2 + 1], ar,  ur[2], ur[3]);
            mma16816(cbr[nt2 * 2],     nai, ui[0], ui[1]);
            mma16816(cbr[nt2 * 2 + 1], nai, ui[2], ui[3]);
            mma16816(cbi[nt2 * 2],     ar,  ui[0], ui[1]);
            mma16816(cbi[nt2 * 2 + 1], ar,  ui[2], ui[3]);
            mma16816(cbi[nt2 * 2],     ai,  ur[0], ur[1]);
            mma16816(cbi[nt2 * 2 + 1], ai,  ur[2], ur[3]);
        }
    }

    // ---- epilogue: probs + residual(global x) + LayerNorm, direct global store ----
    int blockBase = blockIdx.x * 128;
#pragma unroll
    for (int half = 0; half < 2; half++) {
        int rowG = blockBase + warpM + g + half * 8;
        int rowc = rowG < nsamp ? rowG : (nsamp - 1);
        const float* xrow = x + (size_t)rowc * 64;
        float sum = 0.f, sq = 0.f;
#pragma unroll
        for (int nt = 0; nt < 8; nt++) {
            int j = nt * 8 + t4 * 2;
            float2 xv = __ldg((const float2*)(xrow + j));   // 1 sector per quad
            float br0 = cbr[nt][half * 2 + 0];
            float bi0 = cbi[nt][half * 2 + 0];
            float br1 = cbr[nt][half * 2 + 1];
            float bi1 = cbi[nt][half * 2 + 1];
            float v0 = fmaf(br0, br0, bi0 * bi0) + xv.x;
            float v1 = fmaf(br1, br1, bi1 * bi1) + xv.y;
            cbr[nt][half * 2 + 0] = v0;
            cbr[nt][half * 2 + 1] = v1;
            sum += v0 + v1;
            sq = fmaf(v0, v0, fmaf(v1, v1, sq));
        }
        sum += __shfl_xor_sync(0xffffffffu, sum, 1);
        sum += __shfl_xor_sync(0xffffffffu, sum, 2);
        sq  += __shfl_xor_sync(0xffffffffu, sq, 1);
        sq  += __shfl_xor_sync(0xffffffffu, sq, 2);
        float mu = sum * (1.f / 64.f);
        float vv = sq * (1.f / 64.f) - mu * mu;
        float rstd = rsqrtf(vv + 1e-5f);
        if (rowG < nsamp) {
            float* orow = out + (size_t)rowG * 64;
#pragma unroll
            for (int nt = 0; nt < 8; nt++) {
                int j = nt * 8 + t4 * 2;
                float2 ov;
                ov.x = fmaf((cbr[nt][half * 2 + 0] - mu) * rstd, gb[j],     gb[64 + j]);
                ov.y = fmaf((cbr[nt][half * 2 + 1] - mu) * rstd, gb[j + 1], gb[64 + j + 1]);
                *(float2*)(orow + j) = ov;                  // 1 sector per quad
            }
        }
    }
}

// ---------------- launch ----------------
extern "C" void kernel_launch(void* const* d_in, const int* in_sizes, int n_in,
                              void* d_out, int out_size) {
    const float* x      = (const float*)d_in[0];
    const float* var    = (const float*)d_in[1];
    const float* gamma_ = (const float*)d_in[2];
    const float* beta_  = (const float*)d_in[3];
    float* out = (float*)d_out;

    int nsamp = in_sizes[0] / 64;

    cudaFuncSetAttribute(ffb_mma_kernel,
                         cudaFuncAttributeMaxDynamicSharedMemorySize, SMEM_DYN);

    build_W_kernel<<<64, 32>>>(var);

    int blocks = (nsamp + 127) / 128;
    ffb_mma_kernel<<<blocks, 256, SMEM_DYN>>>(x, gamma_, beta_, out, nsamp);
}